// round 15
// baseline (speedup 1.0000x reference)
#include <cuda_runtime.h>
#include <cuda_bf16.h>
#include <math.h>
#include <stdint.h>

#define QL   512
#define BSZ  8
#define HID  1024
#define NH   16
#define HD   64
#define PL   1024
#define IB   (QL*BSZ)
#define JBR  (PL*BSZ)
#define BNH  (BSZ*NH)
#define QKVW 3072
#define SCALEF 0.125f
#define BIGF   1e30f

// -------- fp32 scratch --------
__device__ float g_QKV[IB*QKVW];
__device__ float g_KR[JBR*HID];
__device__ float g_PR[IB*HID];
__device__ float g_EF1[IB*NH*2];
__device__ float g_BW[BNH*QL];
__device__ float g_BR[BNH*PL];

// -------- bf16 split scratch --------
__device__ __nv_bfloat16 g_HA0[IB*HID],  g_HA1[IB*HID];
__device__ __nv_bfloat16 g_PA0[JBR*HID], g_PA1[JBR*HID];
__device__ __nv_bfloat16 g_AOs0[IB*HID], g_AOs1[IB*HID];
__device__ __nv_bfloat16 g_WB0[5*HID*HID], g_WB1[5*HID*HID];
__device__ __nv_bfloat16 g_QKVs0[IB*QKVW], g_QKVs1[IB*QKVW];
__device__ __nv_bfloat16 g_KRs0[JBR*HID],  g_KRs1[JBR*HID];

// ============================ helpers ============================
__device__ __forceinline__ uint32_t smem_u32(const void* p) {
    uint32_t a;
    asm("{ .reg .u64 t; cvta.to.shared.u64 t, %1; cvt.u32.u64 %0, t; }"
        : "=r"(a) : "l"(p));
    return a;
}
#define SWZ(off) ((off) ^ (((off) >> 3) & 0x70))

__device__ __forceinline__ void ldsm_x4(uint32_t* r, uint32_t addr) {
    asm volatile("ldmatrix.sync.aligned.m8n8.x4.shared.b16 {%0,%1,%2,%3}, [%4];"
        : "=r"(r[0]), "=r"(r[1]), "=r"(r[2]), "=r"(r[3]) : "r"(addr));
}
__device__ __forceinline__ void ldsm_x2(uint32_t* r, uint32_t addr) {
    asm volatile("ldmatrix.sync.aligned.m8n8.x2.shared.b16 {%0,%1}, [%2];"
        : "=r"(r[0]), "=r"(r[1]) : "r"(addr));
}
__device__ __forceinline__ void mma_bf16(float* d, const uint32_t* a, const uint32_t* b) {
    asm volatile("mma.sync.aligned.m16n8k16.row.col.f32.bf16.bf16.f32 "
        "{%0,%1,%2,%3}, {%4,%5,%6,%7}, {%8,%9}, {%0,%1,%2,%3};"
        : "+f"(d[0]), "+f"(d[1]), "+f"(d[2]), "+f"(d[3])
        : "r"(a[0]), "r"(a[1]), "r"(a[2]), "r"(a[3]), "r"(b[0]), "r"(b[1]));
}
__device__ __forceinline__ void split2f(float v, __nv_bfloat16& a0, __nv_bfloat16& a1) {
    a0 = __float2bfloat16_rn(v);
    a1 = __float2bfloat16_rn(v - __bfloat162float(a0));
}
__device__ __forceinline__ uint32_t bpack(__nv_bfloat16 lo, __nv_bfloat16 hi) {
    __nv_bfloat162 t = __halves2bfloat162(lo, hi);
    return *(uint32_t*)&t;
}
__device__ __forceinline__ void cpa16(uint32_t d, const void* s) {
    asm volatile("cp.async.cg.shared.global [%0], [%1], 16;" :: "r"(d), "l"(s));
}
__device__ __forceinline__ void cpa4(uint32_t d, const void* s) {
    asm volatile("cp.async.ca.shared.global [%0], [%1], 4;" :: "r"(d), "l"(s));
}
#define CP_COMMIT() asm volatile("cp.async.commit_group;" ::: "memory")
#define CP_WAIT0()  asm volatile("cp.async.wait_group 0;" ::: "memory")

// ============================ split kernels ============================
__global__ void split2_kernel(const float* __restrict__ X,
    __nv_bfloat16* __restrict__ S0, __nv_bfloat16* __restrict__ S1, int n4)
{
    int i = blockIdx.x * blockDim.x + threadIdx.x;
    if (i >= n4) return;
    float4 v = ((const float4*)X)[i];
    __nv_bfloat16 a[4], b[4];
    split2f(v.x, a[0], b[0]);
    split2f(v.y, a[1], b[1]);
    split2f(v.z, a[2], b[2]);
    split2f(v.w, a[3], b[3]);
    uint32_t* p0 = (uint32_t*)S0;
    uint32_t* p1 = (uint32_t*)S1;
    p0[2*i]   = bpack(a[0], a[1]);
    p0[2*i+1] = bpack(a[2], a[3]);
    p1[2*i]   = bpack(b[0], b[1]);
    p1[2*i+1] = bpack(b[2], b[3]);
}

__global__ void tsplit2_kernel(const float* __restrict__ W,
    __nv_bfloat16* __restrict__ T0, __nv_bfloat16* __restrict__ T1)
{
    __shared__ float t[32][33];
    const int n0 = blockIdx.x * 32, k0 = blockIdx.y * 32;
    const int tx = threadIdx.x, ty = threadIdx.y;
    for (int r = ty; r < 32; r += 8)
        t[r][tx] = W[(size_t)(k0 + r) * HID + n0 + tx];
    __syncthreads();
    for (int r = ty; r < 32; r += 8) {
        float v = t[tx][r];
        __nv_bfloat16 a, b; split2f(v, a, b);
        size_t o = (size_t)(n0 + r) * HID + k0 + tx;
        T0[o] = a; T1[o] = b;
    }
}

// ============================ HMMA GEMM (known-good) ============================
#define GEMM_SMEM 65536

__global__ __launch_bounds__(256, 2) void gemm_mma(
    const __nv_bfloat16* __restrict__ A0, const __nv_bfloat16* __restrict__ A1,
    const __nv_bfloat16* __restrict__ B0, const __nv_bfloat16* __restrict__ B1,
    float* __restrict__ C, int M, int N, int K)
{
    extern __shared__ char sm[];
    const uint32_t su = smem_u32(sm);
    const int tid = threadIdx.x, lane = tid & 31, wid = tid >> 5;
    const int wm = (wid >> 2) * 64, wn = (wid & 3) * 32;
    const int m0 = blockIdx.y * 128, n0 = blockIdx.x * 128;

    float acc[4][4][4];
#pragma unroll
    for (int mi = 0; mi < 4; ++mi)
#pragma unroll
        for (int ni = 0; ni < 4; ++ni)
#pragma unroll
            for (int q = 0; q < 4; ++q) acc[mi][ni][q] = 0.f;

    const __nv_bfloat16* Ap[2] = {A0, A1};
    const __nv_bfloat16* Bp[2] = {B0, B1};
    const int a_row = lane & 15, a_kb = (lane >> 4) * 16;
    const int b_row = lane & 7,  b_kb = ((lane >> 3) & 1) * 16;

    for (int k0 = 0; k0 < K; k0 += 64) {
        __syncthreads();
#pragma unroll
        for (int s = 0; s < 2; ++s) {
            const char* ag = (const char*)(Ap[s] + (size_t)m0 * K + k0);
            const char* bg = (const char*)(Bp[s] + (size_t)n0 * K + k0);
            char* at = sm + s * 16384;
            char* bt = sm + 32768 + s * 16384;
#pragma unroll
            for (int i = 0; i < 4; ++i) {
                const int off = (tid + i * 256) * 16;
                const int row = off >> 7, cb = off & 127;
                const size_t g = (size_t)row * K * 2 + cb;
                *(uint4*)(at + SWZ(off)) = *(const uint4*)(ag + g);
                *(uint4*)(bt + SWZ(off)) = *(const uint4*)(bg + g);
            }
        }
        __syncthreads();

        const int asel[3] = {0, 0, 1};
        const int bsel[3] = {0, 1, 0};
#pragma unroll
        for (int t = 0; t < 3; ++t) {
            const uint32_t At = su + asel[t] * 16384;
            const uint32_t Bt = su + 32768 + bsel[t] * 16384;
#pragma unroll
            for (int ks = 0; ks < 4; ++ks) {
                uint32_t af[4][4], bf[4][2];
#pragma unroll
                for (int mi = 0; mi < 4; ++mi) {
                    const int row = wm + mi * 16 + a_row;
                    const int off = row * 128 + ks * 32 + a_kb;
                    ldsm_x4(af[mi], At + SWZ(off));
                }
#pragma unroll
                for (int ni = 0; ni < 4; ++ni) {
                    const int row = wn + ni * 8 + b_row;
                    const int off = row * 128 + ks * 32 + b_kb;
                    ldsm_x2(bf[ni], Bt + SWZ(off));
                }
#pragma unroll
                for (int mi = 0; mi < 4; ++mi)
#pragma unroll
                    for (int ni = 0; ni < 4; ++ni)
                        mma_bf16(acc[mi][ni], af[mi], bf[ni]);
            }
        }
    }

    const int er = lane >> 2, ec = (lane & 3) * 2;
#pragma unroll
    for (int mi = 0; mi < 4; ++mi) {
#pragma unroll
        for (int ni = 0; ni < 4; ++ni) {
            const int row = m0 + wm + mi * 16 + er;
            const int col = n0 + wn + ni * 8 + ec;
            float2 v0 = {acc[mi][ni][0], acc[mi][ni][1]};
            float2 v1 = {acc[mi][ni][2], acc[mi][ni][3]};
            *(float2*)(C + (size_t)row * N + col)       = v0;
            *(float2*)(C + (size_t)(row + 8) * N + col) = v1;
        }
    }
}

// ============================ small precompute kernels ============================
__global__ void ef1_kernel(const float* __restrict__ QKV, const float* __restrict__ rsb,
                           const float* __restrict__ segm, float* __restrict__ EF1)
{
    int w = (blockIdx.x * blockDim.x + threadIdx.x) >> 5;
    int lane = threadIdx.x & 31;
    int n = w & 15, ib = w >> 4;
    const float* qp = QKV + (size_t)ib * QKVW + n * 64;
    const float* bp = rsb + n * 64;
    float q0 = qp[lane] + bp[lane];
    float q1 = qp[lane + 32] + bp[lane + 32];
    float s0 = q0 * segm[n*64 + lane]        + q1 * segm[n*64 + lane + 32];
    float s1 = q0 * segm[1024 + n*64 + lane] + q1 * segm[1024 + n*64 + lane + 32];
#pragma unroll
    for (int o = 16; o; o >>= 1) {
        s0 += __shfl_xor_sync(0xffffffffu, s0, o);
        s1 += __shfl_xor_sync(0xffffffffu, s1, o);
    }
    if (lane == 0) { EF1[w*2] = s0; EF1[w*2 + 1] = s1; }
}

__global__ void rowbias_kernel(const float* __restrict__ X, int stride, int coloff,
                               const float* __restrict__ bias,
                               float* __restrict__ OUT, int JLEN)
{
    int w = (blockIdx.x * blockDim.x + threadIdx.x) >> 5;
    int lane = threadIdx.x & 31;
    int n = w & 15, rem = w >> 4;
    int b = rem & 7, j = rem >> 3;
    const float* xp = X + (size_t)(j * BSZ + b) * stride + coloff + n * 64;
    float v = xp[lane] * bias[n*64 + lane] + xp[lane + 32] * bias[n*64 + lane + 32];
#pragma unroll
    for (int o = 16; o; o >>= 1) v += __shfl_xor_sync(0xffffffffu, v, o);
    if (lane == 0) OUT[(size_t)(b * 16 + n) * JLEN + j] = v;
}

// ============================ fused flash attention (presplit + cp.async double-buffer) ============================
// One CTA per (i-tile of 64, b, n). 8 j-chunks of 64. Band = 127 rows (+1 pad).
// K/R/V/Bw/Br are double-buffered; chunk c+1 prefetched via cp.async during chunk c compute.
#define SA_Q0   0        // 64x64 bf16 x2 splits (single buffer)
#define SA_Q1   8192
#define SA_K    16384    // 2 bufs x (2 splits x 8192) = 32768
#define SA_R    49152    // 2 bufs x (2 splits x 16384) = 65536 (row 127 = pad)
#define SA_V    114688   // 2 bufs x 17408 (fp32 [64][68])
#define SA_SB   149504   // bd' fp32 [64][132]
#define SA_SC   183296   // score/P fp32 [64][68]
#define SA_RM   200704
#define SA_RS   200960
#define SA_RF   201216
#define SA_BW   201472   // 2 bufs x 256
#define SA_BR   201984   // 2 bufs x 512
#define ATTN_SMEM 203008

__device__ __forceinline__ void prefetch_chunk(
    uint32_t su, int bb, int jc0, int gb, int b, int n, int bz, int tid,
    const __nv_bfloat16* QKVs0, const __nv_bfloat16* QKVs1,
    const __nv_bfloat16* KRs0,  const __nv_bfloat16* KRs1,
    const float* QKV, const float* BW, const float* BR)
{
    // K chunk (both splits)
    const uint32_t kb = su + SA_K + bb * 16384;
#pragma unroll
    for (int k = 0; k < 2; ++k) {
        const int off = (tid + k * 256) * 16;
        const int row = off >> 7, cb = off & 127;
        const size_t g = ((size_t)((jc0 + row) * BSZ + b) * QKVW + 1024 + n * 64) * 2 + cb;
        cpa16(kb + SWZ(off),        (const char*)QKVs0 + g);
        cpa16(kb + 8192 + SWZ(off), (const char*)QKVs1 + g);
    }
    // V chunk (fp32, padded stride 68)
    {
        const uint32_t vb = su + SA_V + bb * 17408;
        const int jl = tid >> 2, d0 = (tid & 3) * 16;
        const float* vp = QKV + (size_t)((jc0 + jl) * BSZ + b) * QKVW + 2048 + n * 64 + d0;
#pragma unroll
        for (int u = 0; u < 4; ++u)
            cpa16(vb + (jl * 68 + d0 + u * 4) * 4, vp + u * 4);
    }
    // KR band (rows < 127; row 127 pre-zeroed pad)
    const uint32_t rb = su + SA_R + bb * 32768;
#pragma unroll
    for (int k = 0; k < 4; ++k) {
        const int off = (tid + k * 256) * 16;
        const int row = off >> 7, cb = off & 127;
        if (row < 127) {
            const size_t g = ((size_t)((gb + row) * BSZ + b) * HID + n * 64) * 2 + cb;
            cpa16(rb + SWZ(off),         (const char*)KRs0 + g);
            cpa16(rb + 16384 + SWZ(off), (const char*)KRs1 + g);
        }
    }
    if (tid < 64)  cpa4(su + SA_BW + bb * 256 + tid * 4, BW + (size_t)bz * QL + jc0 + tid);
    if (tid < 127) cpa4(su + SA_BR + bb * 512 + tid * 4, BR + (size_t)bz * PL + gb + tid);
}

__global__ __launch_bounds__(256, 1) void attn_kernel(
    const float* __restrict__ QKV,
    const __nv_bfloat16* __restrict__ QKVs0, const __nv_bfloat16* __restrict__ QKVs1,
    const __nv_bfloat16* __restrict__ KRs0,  const __nv_bfloat16* __restrict__ KRs1,
    const float* __restrict__ EF1, const float* __restrict__ BW,
    const float* __restrict__ BR, const float* __restrict__ seg,
    const float* __restrict__ mask,
    __nv_bfloat16* __restrict__ AOs0, __nv_bfloat16* __restrict__ AOs1)
{
    extern __shared__ char sm[];
    const uint32_t su = smem_u32(sm);
    float* Sb = (float*)(sm + SA_SB);
    float* Sc = (float*)(sm + SA_SC);
    float* rowm = (float*)(sm + SA_RM);
    float* rows = (float*)(sm + SA_RS);
    float* rowf = (float*)(sm + SA_RF);

    const int tid = threadIdx.x, lane = tid & 31, wid = tid >> 5;
    const int i0 = blockIdx.x * 64;
    const int bz = blockIdx.y;            // b*16+n
    const int b = bz >> 4, n = bz & 15;
    const int wy = wid >> 2, wx = wid & 3;
    const int ty = tid >> 4, tx = tid & 15;

    // ---- load Q tile (regular copies; once) ----
#pragma unroll
    for (int k = 0; k < 2; ++k) {
        const int off = (tid + k * 256) * 16;
        const int row = off >> 7, cb = off & 127;
        const size_t g = ((size_t)((i0 + row) * BSZ + b) * QKVW + n * 64) * 2 + cb;
        *(uint4*)(sm + SA_Q0 + SWZ(off)) = *(const uint4*)((const char*)QKVs0 + g);
        *(uint4*)(sm + SA_Q1 + SWZ(off)) = *(const uint4*)((const char*)QKVs1 + g);
    }
    if (tid < 64) { rowm[tid] = -BIGF; rows[tid] = 0.f; }
    // zero KR pad row 127 in both buffers/splits (never overwritten by prefetch)
    if (tid < 32) {
        const int reg = tid >> 3, idx = tid & 7;
        const int bb = reg >> 1, s = reg & 1;
        uint4 z = {0u, 0u, 0u, 0u};
        *(uint4*)(sm + SA_R + bb * 32768 + s * 16384 + SWZ(16256 + idx * 16)) = z;
    }

    float efx[4], efy[4];
#pragma unroll
    for (int m = 0; m < 4; ++m) {
        const int i = i0 + ty * 4 + m;
        const float2 ef = *(const float2*)&EF1[((size_t)(i * BSZ + b) * 16 + n) * 2];
        efx[m] = ef.x; efy[m] = ef.y;
    }

    float O[4][4];
#pragma unroll
    for (int m = 0; m < 4; ++m)
#pragma unroll
        for (int q = 0; q < 4; ++q) O[m][q] = 0.f;

    const int a_row = lane & 15, a_kb = (lane >> 4) * 16;
    const int b_row = lane & 7,  b_kb = ((lane >> 3) & 1) * 16;

    // prefetch chunk 0 into buffer 0
    prefetch_chunk(su, 0, 0, 0 - i0 + 449, b, n, bz, tid,
                   QKVs0, QKVs1, KRs0, KRs1, QKV, BW, BR);
    CP_COMMIT();

    for (int c = 0; c < 8; ++c) {
        const int jc0 = c * 64;
        const int gb = jc0 - i0 + 449;
        CP_WAIT0();
        __syncthreads();   // chunk data ready; previous compute fully done

        if (c < 7) {
            prefetch_chunk(su, (c + 1) & 1, jc0 + 64, gb + 64, b, n, bz, tid,
                           QKVs0, QKVs1, KRs0, KRs1, QKV, BW, BR);
            CP_COMMIT();
        }

        const int cb2 = c & 1;
        const uint32_t Kbase = su + SA_K + cb2 * 16384;
        const uint32_t Rbase = su + SA_R + cb2 * 32768;
        float* Vc  = (float*)(sm + SA_V + cb2 * 17408);
        float* Bws = (float*)(sm + SA_BW + cb2 * 256);
        float* Brs = (float*)(sm + SA_BR + cb2 * 512);

        // ---- HMMA: ac (64x64) and bd' (64x128) ----
        float aac[2][2][4], abd[2][4][4];
#pragma unroll
        for (int mi = 0; mi < 2; ++mi) {
#pragma unroll
            for (int ni = 0; ni < 2; ++ni)
#pragma unroll
                for (int q = 0; q < 4; ++q) aac[mi][ni][q] = 0.f;
#pragma unroll
            for (int ni = 0; ni < 4; ++ni)
#pragma unroll
                for (int q = 0; q < 4; ++q) abd[mi][ni][q] = 0.f;
        }
        const int asel[3] = {0, 0, 1};
        const int bsel[3] = {0, 1, 0};
#pragma unroll
        for (int t = 0; t < 3; ++t) {
            const uint32_t At = su + SA_Q0 + asel[t] * 8192;
            const uint32_t Kt = Kbase + bsel[t] * 8192;
            const uint32_t Rt = Rbase + bsel[t] * 16384;
#pragma unroll
            for (int ks = 0; ks < 4; ++ks) {
                uint32_t af[2][4], bk[2][2], br_[4][2];
#pragma unroll
                for (int mi = 0; mi < 2; ++mi) {
                    const int row = wy * 32 + mi * 16 + a_row;
                    ldsm_x4(af[mi], At + SWZ(row * 128 + ks * 32 + a_kb));
                }
#pragma unroll
                for (int ni = 0; ni < 2; ++ni) {
                    const int row = wx * 16 + ni * 8 + b_row;
                    ldsm_x2(bk[ni], Kt + SWZ(row * 128 + ks * 32 + b_kb));
                }
#pragma unroll
                for (int ni = 0; ni < 4; ++ni) {
                    const int row = wx * 32 + ni * 8 + b_row;
                    ldsm_x2(br_[ni], Rt + SWZ(row * 128 + ks * 32 + b_kb));
                }
#pragma unroll
                for (int mi = 0; mi < 2; ++mi) {
#pragma unroll
                    for (int ni = 0; ni < 2; ++ni) mma_bf16(aac[mi][ni], af[mi], bk[ni]);
#pragma unroll
                    for (int ni = 0; ni < 4; ++ni) mma_bf16(abd[mi][ni], af[mi], br_[ni]);
                }
            }
        }
        // write frags to smem
        const int er = lane >> 2, ec = (lane & 3) * 2;
#pragma unroll
        for (int mi = 0; mi < 2; ++mi) {
            const int r0 = wy * 32 + mi * 16 + er;
#pragma unroll
            for (int ni = 0; ni < 2; ++ni) {
                const int cc = wx * 16 + ni * 8 + ec;
                *(float2*)&Sc[r0 * 68 + cc]       = make_float2(aac[mi][ni][0], aac[mi][ni][1]);
                *(float2*)&Sc[(r0 + 8) * 68 + cc] = make_float2(aac[mi][ni][2], aac[mi][ni][3]);
            }
#pragma unroll
            for (int ni = 0; ni < 4; ++ni) {
                const int cc = wx * 32 + ni * 8 + ec;
                *(float2*)&Sb[r0 * 132 + cc]       = make_float2(abd[mi][ni][0], abd[mi][ni][1]);
                *(float2*)&Sb[(r0 + 8) * 132 + cc] = make_float2(abd[mi][ni][2], abd[mi][ni][3]);
            }
        }
        __syncthreads();

        // ---- assemble full scores into Sc ----
#pragma unroll
        for (int m = 0; m < 4; ++m) {
            const int il = ty * 4 + m;
            const int i = i0 + il;
#pragma unroll
            for (int q = 0; q < 4; ++q) {
                const int jl = tx * 4 + q;
                const int j = jc0 + jl;
                const int t = jl - il + 63;
                const size_t ij = (size_t)(i * QL + j) * BSZ + b;
                const float2 sg = *(const float2*)&seg[ij * 2];
                const float mk = mask[ij];
                float s = Sc[il * 68 + jl] + Sb[il * 132 + t] + Bws[jl] + Brs[t]
                        + sg.x * efx[m] + sg.y * efy[m];
                Sc[il * 68 + jl] = s * SCALEF - BIGF * mk;
            }
        }
        __syncthreads();

        // ---- online softmax row stats ----
        {
            const int r = wid * 8 + (lane >> 2);
            const int c4 = lane & 3;
            float cmax = -BIGF;
#pragma unroll
            for (int u = 0; u < 16; ++u)
                cmax = fmaxf(cmax, Sc[r * 68 + c4 * 16 + u]);
            cmax = fmaxf(cmax, __shfl_xor_sync(0xffffffffu, cmax, 1));
            cmax = fmaxf(cmax, __shfl_xor_sync(0xffffffffu, cmax, 2));
            const float m_old = rowm[r];
            const float m_new = fmaxf(m_old, cmax);
            float psum = 0.f;
#pragma unroll
            for (int u = 0; u < 16; ++u) {
                const int idx = r * 68 + c4 * 16 + u;
                const float p = __expf(Sc[idx] - m_new);
                Sc[idx] = p;
                psum += p;
            }
            psum += __shfl_xor_sync(0xffffffffu, psum, 1);
            psum += __shfl_xor_sync(0xffffffffu, psum, 2);
            if (c4 == 0) {
                const float f = __expf(m_old - m_new);
                rowm[r] = m_new;
                rows[r] = rows[r] * f + psum;
                rowf[r] = f;
            }
        }
        __syncthreads();

        // ---- AV accumulate (SIMT fp32) ----
        {
            float fr[4];
#pragma unroll
            for (int m = 0; m < 4; ++m) {
                fr[m] = rowf[ty * 4 + m];
#pragma unroll
                for (int q = 0; q < 4; ++q) O[m][q] *= fr[m];
            }
#pragma unroll 4
            for (int jl = 0; jl < 64; ++jl) {
                float p[4], vv[4];
#pragma unroll
                for (int m = 0; m < 4; ++m) p[m] = Sc[(ty * 4 + m) * 68 + jl];
#pragma unroll
                for (int q = 0; q < 4; ++q) vv[q] = Vc[jl * 68 + tx * 4 + q];
#pragma unroll
                for (int m = 0; m < 4; ++m)
#pragma unroll
                    for (int q = 0; q < 4; ++q)
                        O[m][q] += p[m] * vv[q];
            }
        }
    }

    // ---- finalize: normalize + direct bf16 split to AOs0/AOs1 ----
    __syncthreads();
#pragma unroll
    for (int m = 0; m < 4; ++m) {
        const int il = ty * 4 + m;
        const float inv = 1.f / rows[il];
        __nv_bfloat16 a[4], c[4];
#pragma unroll
        for (int q = 0; q < 4; ++q) split2f(O[m][q] * inv, a[q], c[q]);
        const size_t o = ((size_t)((i0 + il) * BSZ + b)) * HID + n * 64 + tx * 4;
        *(uint32_t*)&AOs0[o]     = bpack(a[0], a[1]);
        *(uint32_t*)&AOs0[o + 2] = bpack(a[2], a[3]);
        *(uint32_t*)&AOs1[o]     = bpack(c[0], c[1]);
        *(uint32_t*)&AOs1[o + 2] = bpack(c[2], c[3]);
    }
}

// ============================ LayerNorm ============================
__global__ void ln_kernel(const float* __restrict__ PR, const float* __restrict__ HS,
                          const float* __restrict__ gamma, const float* __restrict__ beta,
                          float* __restrict__ out)
{
    __shared__ float sred[2][8];
    const int row = blockIdx.x;
    const int tid = threadIdx.x;
    const float* pr = PR + (size_t)row * HID;
    const float* hs = HS + (size_t)row * HID;
    float x[4], s = 0.f, s2 = 0.f;
#pragma unroll
    for (int t = 0; t < 4; ++t) {
        int c = tid + 256 * t;
        float v = pr[c] + hs[c];
        x[t] = v; s += v; s2 += v * v;
    }
#pragma unroll
    for (int o = 16; o; o >>= 1) {
        s  += __shfl_xor_sync(0xffffffffu, s,  o);
        s2 += __shfl_xor_sync(0xffffffffu, s2, o);
    }
    if ((tid & 31) == 0) { sred[0][tid >> 5] = s; sred[1][tid >> 5] = s2; }
    __syncthreads();
    if (tid < 32) {
        float a = (tid < 8) ? sred[0][tid] : 0.f;
        float b2 = (tid < 8) ? sred[1][tid] : 0.f;
#pragma unroll
        for (int o = 4; o; o >>= 1) {
            a  += __shfl_xor_sync(0xffffffffu, a,  o);
            b2 += __shfl_xor_sync(0xffffffffu, b2, o);
        }
        if (tid == 0) { sred[0][0] = a; sred[1][0] = b2; }
    }
    __syncthreads();
    const float mean = sred[0][0] * (1.f / 1024.f);
    const float var  = sred[1][0] * (1.f / 1024.f) - mean * mean;
    const float inv  = rsqrtf(var + 1e-5f);
#pragma unroll
    for (int t = 0; t < 4; ++t) {
        int c = tid + 256 * t;
        out[(size_t)row * HID + c] = (x[t] - mean) * inv * gamma[c] + beta[c];
    }
}

// ============================ launch ============================
extern "C" void kernel_launch(void* const* d_in, const int* in_sizes, int n_in,
                              void* d_out, int out_size)
{
    (void)in_sizes; (void)n_in; (void)out_size;
    const float* hs    = (const float*)d_in[0];
    const float* pos   = (const float*)d_in[1];
    const float* seg   = (const float*)d_in[2];
    const float* mask  = (const float*)d_in[3];
    const float* wq    = (const float*)d_in[4];
    const float* wk    = (const float*)d_in[5];
    const float* wv    = (const float*)d_in[6];
    const float* wr    = (const float*)d_in[7];
    const float* wo    = (const float*)d_in[8];
    const float* rwb   = (const float*)d_in[9];
    const float* rrb   = (const float*)d_in[10];
    const float* rsb   = (const float*)d_in[11];
    const float* segm  = (const float*)d_in[12];
    const float* gamma = (const float*)d_in[13];
    const float* beta  = (const float*)d_in[14];
    float* out = (float*)d_out;

    float *QKVd, *KRd, *PRd, *EF1d, *BWd, *BRd;
    cudaGetSymbolAddress((void**)&QKVd, g_QKV);
    cudaGetSymbolAddress((void**)&KRd, g_KR);
    cudaGetSymbolAddress((void**)&PRd, g_PR);
    cudaGetSymbolAddress((void**)&EF1d, g_EF1);
    cudaGetSymbolAddress((void**)&BWd, g_BW);
    cudaGetSymbolAddress((void**)&BRd, g_BR);

    __nv_bfloat16 *HA0, *HA1, *PA0, *PA1, *AOs0, *AOs1, *WB0, *WB1;
    __nv_bfloat16 *QKVs0, *QKVs1, *KRs0, *KRs1;
    cudaGetSymbolAddress((void**)&HA0, g_HA0);
    cudaGetSymbolAddress((void**)&HA1, g_HA1);
    cudaGetSymbolAddress((void**)&PA0, g_PA0);
    cudaGetSymbolAddress((void**)&PA1, g_PA1);
    cudaGetSymbolAddress((void**)&AOs0, g_AOs0);
    cudaGetSymbolAddress((void**)&AOs1, g_AOs1);
    cudaGetSymbolAddress((void**)&WB0, g_WB0);
    cudaGetSymbolAddress((void**)&WB1, g_WB1);
    cudaGetSymbolAddress((void**)&QKVs0, g_QKVs0);
    cudaGetSymbolAddress((void**)&QKVs1, g_QKVs1);
    cudaGetSymbolAddress((void**)&KRs0, g_KRs0);
    cudaGetSymbolAddress((void**)&KRs1, g_KRs1);

    cudaFuncSetAttribute(gemm_mma, cudaFuncAttributeMaxDynamicSharedMemorySize, GEMM_SMEM);
    cudaFuncSetAttribute(attn_kernel, cudaFuncAttributeMaxDynamicSharedMemorySize, ATTN_SMEM);

    const size_t WSZ = (size_t)HID * HID;

    // Splits (inputs + weights)
    split2_kernel<<<(IB*HID/4 + 255)/256, 256>>>(hs,  HA0, HA1, IB*HID/4);
    split2_kernel<<<(JBR*HID/4 + 255)/256, 256>>>(pos, PA0, PA1, JBR*HID/4);
    dim3 gt(32, 32), bt(32, 8);
    tsplit2_kernel<<<gt, bt>>>(wq, WB0 + 0*WSZ, WB1 + 0*WSZ);
    tsplit2_kernel<<<gt, bt>>>(wk, WB0 + 1*WSZ, WB1 + 1*WSZ);
    tsplit2_kernel<<<gt, bt>>>(wv, WB0 + 2*WSZ, WB1 + 2*WSZ);
    tsplit2_kernel<<<gt, bt>>>(wr, WB0 + 3*WSZ, WB1 + 3*WSZ);
    split2_kernel<<<(HID*HID/4 + 255)/256, 256>>>(wo, WB0 + 4*WSZ, WB1 + 4*WSZ, HID*HID/4);

    // Fused QKV projection (N = 3072) + KR projection
    dim3 gqkv(QKVW / 128, IB / 128);   // (24, 32)
    gemm_mma<<<gqkv, 256, GEMM_SMEM>>>(HA0, HA1, WB0, WB1, QKVd, IB, QKVW, HID);
    dim3 gr(8, 64);
    gemm_mma<<<gr, 256, GEMM_SMEM>>>(PA0, PA1, WB0+3*WSZ, WB1+3*WSZ, KRd, JBR, HID, HID);

    // Pre-split activations for attention
    split2_kernel<<<(IB*QKVW/4 + 255)/256, 256>>>(QKVd, QKVs0, QKVs1, IB*QKVW/4);
    split2_kernel<<<(JBR*HID/4 + 255)/256, 256>>>(KRd, KRs0, KRs1, JBR*HID/4);

    // Bias precomputes
    ef1_kernel    <<<IB * NH / 4, 128>>>(QKVd, rsb, segm, EF1d);
    rowbias_kernel<<<QL * BSZ * NH / 4, 128>>>(QKVd, QKVW, 1024, rwb, BWd, QL);
    rowbias_kernel<<<PL * BSZ * NH / 4, 128>>>(KRd,  HID,  0,    rrb, BRd, PL);

    // Fused flash attention (cp.async double-buffered loads)
    dim3 ga(QL / 64, BNH);             // (8, 128)
    attn_kernel<<<ga, 256, ATTN_SMEM>>>(QKVd, QKVs0, QKVs1, KRs0, KRs1,
                                        EF1d, BWd, BRd, seg, mask, AOs0, AOs1);

    // Output projection (HMMA) + LN
    dim3 go(8, 32);
    gemm_mma<<<go, 256, GEMM_SMEM>>>(AOs0, AOs1, WB0+4*WSZ, WB1+4*WSZ, PRd, IB, HID, HID);
    ln_kernel<<<IB, 256>>>(PRd, hs, gamma, beta, out);
}

// round 16
// speedup vs baseline: 1.5306x; 1.5306x over previous
#include <cuda_runtime.h>
#include <cuda_bf16.h>
#include <math.h>
#include <stdint.h>

#define QL   512
#define BSZ  8
#define HID  1024
#define NH   16
#define HD   64
#define PL   1024
#define IB   (QL*BSZ)
#define JBR  (PL*BSZ)
#define BNH  (BSZ*NH)
#define QKVW 3072
#define SCALEF 0.125f
#define BIGF   1e30f

// -------- fp32 scratch --------
__device__ float g_QKV[IB*QKVW];
__device__ float g_KR[JBR*HID];
__device__ float g_PR[IB*HID];
__device__ float g_EF1[IB*NH*2];
__device__ float g_BW[BNH*QL];
__device__ float g_BR[BNH*PL];

// -------- bf16 scratch (single precision level; no split) --------
__device__ __nv_bfloat16 g_HA[IB*HID];
__device__ __nv_bfloat16 g_PA[JBR*HID];
__device__ __nv_bfloat16 g_AOb[IB*HID];
__device__ __nv_bfloat16 g_WB[5*HID*HID];
__device__ __nv_bfloat16 g_QKVb[IB*QKVW];
__device__ __nv_bfloat16 g_KRb[JBR*HID];

// ============================ helpers ============================
__device__ __forceinline__ uint32_t smem_u32(const void* p) {
    uint32_t a;
    asm("{ .reg .u64 t; cvta.to.shared.u64 t, %1; cvt.u32.u64 %0, t; }"
        : "=r"(a) : "l"(p));
    return a;
}
#define SWZ(off) ((off) ^ (((off) >> 3) & 0x70))

__device__ __forceinline__ void ldsm_x4(uint32_t* r, uint32_t addr) {
    asm volatile("ldmatrix.sync.aligned.m8n8.x4.shared.b16 {%0,%1,%2,%3}, [%4];"
        : "=r"(r[0]), "=r"(r[1]), "=r"(r[2]), "=r"(r[3]) : "r"(addr));
}
__device__ __forceinline__ void ldsm_x2(uint32_t* r, uint32_t addr) {
    asm volatile("ldmatrix.sync.aligned.m8n8.x2.shared.b16 {%0,%1}, [%2];"
        : "=r"(r[0]), "=r"(r[1]) : "r"(addr));
}
__device__ __forceinline__ void mma_bf16(float* d, const uint32_t* a, const uint32_t* b) {
    asm volatile("mma.sync.aligned.m16n8k16.row.col.f32.bf16.bf16.f32 "
        "{%0,%1,%2,%3}, {%4,%5,%6,%7}, {%8,%9}, {%0,%1,%2,%3};"
        : "+f"(d[0]), "+f"(d[1]), "+f"(d[2]), "+f"(d[3])
        : "r"(a[0]), "r"(a[1]), "r"(a[2]), "r"(a[3]), "r"(b[0]), "r"(b[1]));
}
__device__ __forceinline__ uint32_t bpack(__nv_bfloat16 lo, __nv_bfloat16 hi) {
    __nv_bfloat162 t = __halves2bfloat162(lo, hi);
    return *(uint32_t*)&t;
}

// ============================ convert kernels ============================
__global__ void cvt_kernel(const float* __restrict__ X,
                           __nv_bfloat16* __restrict__ S, int n4)
{
    int i = blockIdx.x * blockDim.x + threadIdx.x;
    if (i >= n4) return;
    float4 v = ((const float4*)X)[i];
    uint32_t* p = (uint32_t*)S;
    p[2*i]   = bpack(__float2bfloat16_rn(v.x), __float2bfloat16_rn(v.y));
    p[2*i+1] = bpack(__float2bfloat16_rn(v.z), __float2bfloat16_rn(v.w));
}

// transpose + convert: W [1024(k) x 1024(n)] -> T [n][k] bf16
__global__ void tcvt_kernel(const float* __restrict__ W,
                            __nv_bfloat16* __restrict__ T)
{
    __shared__ float t[32][33];
    const int n0 = blockIdx.x * 32, k0 = blockIdx.y * 32;
    const int tx = threadIdx.x, ty = threadIdx.y;
    for (int r = ty; r < 32; r += 8)
        t[r][tx] = W[(size_t)(k0 + r) * HID + n0 + tx];
    __syncthreads();
    for (int r = ty; r < 32; r += 8)
        T[(size_t)(n0 + r) * HID + k0 + tx] = __float2bfloat16_rn(t[tx][r]);
}

// ============================ HMMA GEMM (single bf16) ============================
// C[M,N] fp32 = A[M,K] * B[N,K]^T. Tile 128x128, K-chunk 64, 8 warps 64x32.
#define GEMM_SMEM 32768

__global__ __launch_bounds__(256, 2) void gemm_mma(
    const __nv_bfloat16* __restrict__ A, const __nv_bfloat16* __restrict__ B,
    float* __restrict__ C, int M, int N, int K)
{
    extern __shared__ char sm[];
    const uint32_t su = smem_u32(sm);
    const int tid = threadIdx.x, lane = tid & 31, wid = tid >> 5;
    const int wm = (wid >> 2) * 64, wn = (wid & 3) * 32;
    const int m0 = blockIdx.y * 128, n0 = blockIdx.x * 128;

    float acc[4][4][4];
#pragma unroll
    for (int mi = 0; mi < 4; ++mi)
#pragma unroll
        for (int ni = 0; ni < 4; ++ni)
#pragma unroll
            for (int q = 0; q < 4; ++q) acc[mi][ni][q] = 0.f;

    const int a_row = lane & 15, a_kb = (lane >> 4) * 16;
    const int b_row = lane & 7,  b_kb = ((lane >> 3) & 1) * 16;

    for (int k0 = 0; k0 < K; k0 += 64) {
        __syncthreads();
        const char* ag = (const char*)(A + (size_t)m0 * K + k0);
        const char* bg = (const char*)(B + (size_t)n0 * K + k0);
#pragma unroll
        for (int i = 0; i < 4; ++i) {
            const int off = (tid + i * 256) * 16;       // < 16384
            const int row = off >> 7, cb = off & 127;
            const size_t g = (size_t)row * K * 2 + cb;
            *(uint4*)(sm + SWZ(off))         = *(const uint4*)(ag + g);
            *(uint4*)(sm + 16384 + SWZ(off)) = *(const uint4*)(bg + g);
        }
        __syncthreads();

#pragma unroll
        for (int ks = 0; ks < 4; ++ks) {
            uint32_t af[4][4], bf[4][2];
#pragma unroll
            for (int mi = 0; mi < 4; ++mi) {
                const int row = wm + mi * 16 + a_row;
                ldsm_x4(af[mi], su + SWZ(row * 128 + ks * 32 + a_kb));
            }
#pragma unroll
            for (int ni = 0; ni < 4; ++ni) {
                const int row = wn + ni * 8 + b_row;
                ldsm_x2(bf[ni], su + 16384 + SWZ(row * 128 + ks * 32 + b_kb));
            }
#pragma unroll
            for (int mi = 0; mi < 4; ++mi)
#pragma unroll
                for (int ni = 0; ni < 4; ++ni)
                    mma_bf16(acc[mi][ni], af[mi], bf[ni]);
        }
    }

    const int er = lane >> 2, ec = (lane & 3) * 2;
#pragma unroll
    for (int mi = 0; mi < 4; ++mi) {
#pragma unroll
        for (int ni = 0; ni < 4; ++ni) {
            const int row = m0 + wm + mi * 16 + er;
            const int col = n0 + wn + ni * 8 + ec;
            float2 v0 = {acc[mi][ni][0], acc[mi][ni][1]};
            float2 v1 = {acc[mi][ni][2], acc[mi][ni][3]};
            *(float2*)(C + (size_t)row * N + col)       = v0;
            *(float2*)(C + (size_t)(row + 8) * N + col) = v1;
        }
    }
}

// ============================ small precompute kernels ============================
__global__ void ef1_kernel(const float* __restrict__ QKV, const float* __restrict__ rsb,
                           const float* __restrict__ segm, float* __restrict__ EF1)
{
    int w = (blockIdx.x * blockDim.x + threadIdx.x) >> 5;
    int lane = threadIdx.x & 31;
    int n = w & 15, ib = w >> 4;
    const float* qp = QKV + (size_t)ib * QKVW + n * 64;
    const float* bp = rsb + n * 64;
    float q0 = qp[lane] + bp[lane];
    float q1 = qp[lane + 32] + bp[lane + 32];
    float s0 = q0 * segm[n*64 + lane]        + q1 * segm[n*64 + lane + 32];
    float s1 = q0 * segm[1024 + n*64 + lane] + q1 * segm[1024 + n*64 + lane + 32];
#pragma unroll
    for (int o = 16; o; o >>= 1) {
        s0 += __shfl_xor_sync(0xffffffffu, s0, o);
        s1 += __shfl_xor_sync(0xffffffffu, s1, o);
    }
    if (lane == 0) { EF1[w*2] = s0; EF1[w*2 + 1] = s1; }
}

__global__ void rowbias_kernel(const float* __restrict__ X, int stride, int coloff,
                               const float* __restrict__ bias,
                               float* __restrict__ OUT, int JLEN)
{
    int w = (blockIdx.x * blockDim.x + threadIdx.x) >> 5;
    int lane = threadIdx.x & 31;
    int n = w & 15, rem = w >> 4;
    int b = rem & 7, j = rem >> 3;
    const float* xp = X + (size_t)(j * BSZ + b) * stride + coloff + n * 64;
    float v = xp[lane] * bias[n*64 + lane] + xp[lane + 32] * bias[n*64 + lane + 32];
#pragma unroll
    for (int o = 16; o; o >>= 1) v += __shfl_xor_sync(0xffffffffu, v, o);
    if (lane == 0) OUT[(size_t)(b * 16 + n) * JLEN + j] = v;
}

// ============================ fused flash attention (single bf16, i-tile 64, occ 2) ============================
#define SA_Q    0        // 64x64 bf16 = 8KB
#define SA_K    8192     // 64x64 bf16
#define SA_R    16384    // 128x64 bf16 = 16KB (row 127 = pad)
#define SA_SB   32768    // bd' fp32 [64][132] = 33792
#define SA_SC   66560    // score/P fp32 [64][68] = 17408
#define SA_VC   83968    // V fp32 [64][68] = 17408
#define SA_RM   101376
#define SA_RS   101632
#define SA_RF   101888
#define SA_BW   102144
#define SA_BR   102400   // [127] + pad
#define ATTN_SMEM 102912

__global__ __launch_bounds__(256, 2) void attn_kernel(
    const float* __restrict__ QKV,
    const __nv_bfloat16* __restrict__ QKVb, const __nv_bfloat16* __restrict__ KRb,
    const float* __restrict__ EF1, const float* __restrict__ BW,
    const float* __restrict__ BR, const float* __restrict__ seg,
    const float* __restrict__ mask,
    __nv_bfloat16* __restrict__ AOb)
{
    extern __shared__ char sm[];
    const uint32_t su = smem_u32(sm);
    float* Sb = (float*)(sm + SA_SB);
    float* Sc = (float*)(sm + SA_SC);
    float* Vc = (float*)(sm + SA_VC);
    float* rowm = (float*)(sm + SA_RM);
    float* rows = (float*)(sm + SA_RS);
    float* rowf = (float*)(sm + SA_RF);
    float* Bws  = (float*)(sm + SA_BW);
    float* Brs  = (float*)(sm + SA_BR);

    const int tid = threadIdx.x, lane = tid & 31, wid = tid >> 5;
    const int i0 = blockIdx.x * 64;
    const int bz = blockIdx.y;
    const int b = bz >> 4, n = bz & 15;
    const int wy = wid >> 2, wx = wid & 3;
    const int ty = tid >> 4, tx = tid & 15;

    // ---- load Q tile ----
    {
        const int off = tid * 16 * 2;  // 2 x 16B per thread, contiguous pairs
        const int off0 = tid * 32;
        const int row = off0 >> 7, cb = off0 & 127;
        const size_t g = ((size_t)((i0 + row) * BSZ + b) * QKVW + n * 64) * 2 + cb;
        *(uint4*)(sm + SA_Q + SWZ(off0))      = *(const uint4*)((const char*)QKVb + g);
        *(uint4*)(sm + SA_Q + SWZ(off0 + 16)) = *(const uint4*)((const char*)QKVb + g + 16);
        (void)off;
    }
    if (tid < 64) { rowm[tid] = -BIGF; rows[tid] = 0.f; }

    float efx[4], efy[4];
#pragma unroll
    for (int m = 0; m < 4; ++m) {
        const int i = i0 + ty * 4 + m;
        const float2 ef = *(const float2*)&EF1[((size_t)(i * BSZ + b) * 16 + n) * 2];
        efx[m] = ef.x; efy[m] = ef.y;
    }

    float O[4][4];
#pragma unroll
    for (int m = 0; m < 4; ++m)
#pragma unroll
        for (int q = 0; q < 4; ++q) O[m][q] = 0.f;

    const int a_row = lane & 15, a_kb = (lane >> 4) * 16;
    const int b_row = lane & 7,  b_kb = ((lane >> 3) & 1) * 16;

    for (int jc0 = 0; jc0 < QL; jc0 += 64) {
        const int gb = jc0 - i0 + 449;    // in [1, 897]
        __syncthreads();

        // ---- K chunk ----
        {
            const int off0 = tid * 32;
            const int row = off0 >> 7, cb = off0 & 127;
            const size_t g = ((size_t)((jc0 + row) * BSZ + b) * QKVW + 1024 + n * 64) * 2 + cb;
            *(uint4*)(sm + SA_K + SWZ(off0))      = *(const uint4*)((const char*)QKVb + g);
            *(uint4*)(sm + SA_K + SWZ(off0 + 16)) = *(const uint4*)((const char*)QKVb + g + 16);
        }
        // ---- V chunk (fp32) ----
        {
            const int jl = tid >> 2, d0 = (tid & 3) * 16;
            const float* vp = QKV + (size_t)((jc0 + jl) * BSZ + b) * QKVW + 2048 + n * 64 + d0;
#pragma unroll
            for (int u = 0; u < 4; ++u)
                *(float4*)&Vc[jl * 68 + d0 + u * 4] = *(const float4*)(vp + u * 4);
        }
        // ---- KR band 127 rows (row 127 pad zero) ----
#pragma unroll
        for (int k = 0; k < 2; ++k) {
            const int off0 = (tid + k * 256) * 32;   // < 16384
            const int row = off0 >> 7, cb = off0 & 127;
            if (row < 127) {
                const size_t g = ((size_t)((gb + row) * BSZ + b) * HID + n * 64) * 2 + cb;
                *(uint4*)(sm + SA_R + SWZ(off0))      = *(const uint4*)((const char*)KRb + g);
                *(uint4*)(sm + SA_R + SWZ(off0 + 16)) = *(const uint4*)((const char*)KRb + g + 16);
            } else {
                uint4 z = {0u, 0u, 0u, 0u};
                *(uint4*)(sm + SA_R + SWZ(off0))      = z;
                *(uint4*)(sm + SA_R + SWZ(off0 + 16)) = z;
            }
        }
        if (tid < 64)  Bws[tid] = BW[(size_t)bz * QL + jc0 + tid];
        if (tid < 127) Brs[tid] = BR[(size_t)bz * PL + gb + tid];
        __syncthreads();

        // ---- HMMA: ac (64x64) and bd' (64x128), single bf16 term ----
        float aac[2][2][4], abd[2][4][4];
#pragma unroll
        for (int mi = 0; mi < 2; ++mi) {
#pragma unroll
            for (int ni = 0; ni < 2; ++ni)
#pragma unroll
                for (int q = 0; q < 4; ++q) aac[mi][ni][q] = 0.f;
#pragma unroll
            for (int ni = 0; ni < 4; ++ni)
#pragma unroll
                for (int q = 0; q < 4; ++q) abd[mi][ni][q] = 0.f;
        }
#pragma unroll
        for (int ks = 0; ks < 4; ++ks) {
            uint32_t af[2][4], bk[2][2], br_[4][2];
#pragma unroll
            for (int mi = 0; mi < 2; ++mi) {
                const int row = wy * 32 + mi * 16 + a_row;
                ldsm_x4(af[mi], su + SA_Q + SWZ(row * 128 + ks * 32 + a_kb));
            }
#pragma unroll
            for (int ni = 0; ni < 2; ++ni) {
                const int row = wx * 16 + ni * 8 + b_row;
                ldsm_x2(bk[ni], su + SA_K + SWZ(row * 128 + ks * 32 + b_kb));
            }
#pragma unroll
            for (int ni = 0; ni < 4; ++ni) {
                const int row = wx * 32 + ni * 8 + b_row;
                ldsm_x2(br_[ni], su + SA_R + SWZ(row * 128 + ks * 32 + b_kb));
            }
#pragma unroll
            for (int mi = 0; mi < 2; ++mi) {
#pragma unroll
                for (int ni = 0; ni < 2; ++ni) mma_bf16(aac[mi][ni], af[mi], bk[ni]);
#pragma unroll
                for (int ni = 0; ni < 4; ++ni) mma_bf16(abd[mi][ni], af[mi], br_[ni]);
            }
        }
        // write frags to smem
        const int er = lane >> 2, ec = (lane & 3) * 2;
#pragma unroll
        for (int mi = 0; mi < 2; ++mi) {
            const int r0 = wy * 32 + mi * 16 + er;
#pragma unroll
            for (int ni = 0; ni < 2; ++ni) {
                const int cc = wx * 16 + ni * 8 + ec;
                *(float2*)&Sc[r0 * 68 + cc]       = make_float2(aac[mi][ni][0], aac[mi][ni][1]);
                *(float2*)&Sc[(r0 + 8) * 68 + cc] = make_float2(aac[mi][ni][2], aac[mi][ni][3]);
            }
#pragma unroll
            for (int ni = 0; ni < 4; ++ni) {
                const int cc = wx * 32 + ni * 8 + ec;
                *(float2*)&Sb[r0 * 132 + cc]       = make_float2(abd[mi][ni][0], abd[mi][ni][1]);
                *(float2*)&Sb[(r0 + 8) * 132 + cc] = make_float2(abd[mi][ni][2], abd[mi][ni][3]);
            }
        }
        __syncthreads();

        // ---- assemble full scores into Sc ----
#pragma unroll
        for (int m = 0; m < 4; ++m) {
            const int il = ty * 4 + m;
            const int i = i0 + il;
#pragma unroll
            for (int q = 0; q < 4; ++q) {
                const int jl = tx * 4 + q;
                const int j = jc0 + jl;
                const int t = jl - il + 63;
                const size_t ij = (size_t)(i * QL + j) * BSZ + b;
                const float2 sg = *(const float2*)&seg[ij * 2];
                const float mk = mask[ij];
                float s = Sc[il * 68 + jl] + Sb[il * 132 + t] + Bws[jl] + Brs[t]
                        + sg.x * efx[m] + sg.y * efy[m];
                Sc[il * 68 + jl] = s * SCALEF - BIGF * mk;
            }
        }
        __syncthreads();

        // ---- online softmax row stats ----
        {
            const int r = wid * 8 + (lane >> 2);
            const int c4 = lane & 3;
            float cmax = -BIGF;
#pragma unroll
            for (int u = 0; u < 16; ++u)
                cmax = fmaxf(cmax, Sc[r * 68 + c4 * 16 + u]);
            cmax = fmaxf(cmax, __shfl_xor_sync(0xffffffffu, cmax, 1));
            cmax = fmaxf(cmax, __shfl_xor_sync(0xffffffffu, cmax, 2));
            const float m_old = rowm[r];
            const float m_new = fmaxf(m_old, cmax);
            float psum = 0.f;
#pragma unroll
            for (int u = 0; u < 16; ++u) {
                const int idx = r * 68 + c4 * 16 + u;
                const float p = __expf(Sc[idx] - m_new);
                Sc[idx] = p;
                psum += p;
            }
            psum += __shfl_xor_sync(0xffffffffu, psum, 1);
            psum += __shfl_xor_sync(0xffffffffu, psum, 2);
            if (c4 == 0) {
                const float f = __expf(m_old - m_new);
                rowm[r] = m_new;
                rows[r] = rows[r] * f + psum;
                rowf[r] = f;
            }
        }
        __syncthreads();

        // ---- AV accumulate (SIMT fp32) ----
        {
            float fr[4];
#pragma unroll
            for (int m = 0; m < 4; ++m) {
                fr[m] = rowf[ty * 4 + m];
#pragma unroll
                for (int q = 0; q < 4; ++q) O[m][q] *= fr[m];
            }
#pragma unroll 4
            for (int jl = 0; jl < 64; ++jl) {
                float p[4], vv[4];
#pragma unroll
                for (int m = 0; m < 4; ++m) p[m] = Sc[(ty * 4 + m) * 68 + jl];
#pragma unroll
                for (int q = 0; q < 4; ++q) vv[q] = Vc[jl * 68 + tx * 4 + q];
#pragma unroll
                for (int m = 0; m < 4; ++m)
#pragma unroll
                    for (int q = 0; q < 4; ++q)
                        O[m][q] += p[m] * vv[q];
            }
        }
    }

    // ---- finalize: normalize + bf16 convert to AOb ----
    __syncthreads();
#pragma unroll
    for (int m = 0; m < 4; ++m) {
        const int il = ty * 4 + m;
        const float inv = 1.f / rows[il];
        const size_t o = ((size_t)((i0 + il) * BSZ + b)) * HID + n * 64 + tx * 4;
        *(uint32_t*)&AOb[o]     = bpack(__float2bfloat16_rn(O[m][0] * inv),
                                        __float2bfloat16_rn(O[m][1] * inv));
        *(uint32_t*)&AOb[o + 2] = bpack(__float2bfloat16_rn(O[m][2] * inv),
                                        __float2bfloat16_rn(O[m][3] * inv));
    }
}

// ============================ LayerNorm ============================
__global__ void ln_kernel(const float* __restrict__ PR, const float* __restrict__ HS,
                          const float* __restrict__ gamma, const float* __restrict__ beta,
                          float* __restrict__ out)
{
    __shared__ float sred[2][8];
    const int row = blockIdx.x;
    const int tid = threadIdx.x;
    const float* pr = PR + (size_t)row * HID;
    const float* hs = HS + (size_t)row * HID;
    float x[4], s = 0.f, s2 = 0.f;
#pragma unroll
    for (int t = 0; t < 4; ++t) {
        int c = tid + 256 * t;
        float v = pr[c] + hs[c];
        x[t] = v; s += v; s2 += v * v;
    }
#pragma unroll
    for (int o = 16; o; o >>= 1) {
        s  += __shfl_xor_sync(0xffffffffu, s,  o);
        s2 += __shfl_xor_sync(0xffffffffu, s2, o);
    }
    if ((tid & 31) == 0) { sred[0][tid >> 5] = s; sred[1][tid >> 5] = s2; }
    __syncthreads();
    if (tid < 32) {
        float a = (tid < 8) ? sred[0][tid] : 0.f;
        float b2 = (tid < 8) ? sred[1][tid] : 0.f;
#pragma unroll
        for (int o = 4; o; o >>= 1) {
            a  += __shfl_xor_sync(0xffffffffu, a,  o);
            b2 += __shfl_xor_sync(0xffffffffu, b2, o);
        }
        if (tid == 0) { sred[0][0] = a; sred[1][0] = b2; }
    }
    __syncthreads();
    const float mean = sred[0][0] * (1.f / 1024.f);
    const float var  = sred[1][0] * (1.f / 1024.f) - mean * mean;
    const float inv  = rsqrtf(var + 1e-5f);
#pragma unroll
    for (int t = 0; t < 4; ++t) {
        int c = tid + 256 * t;
        out[(size_t)row * HID + c] = (x[t] - mean) * inv * gamma[c] + beta[c];
    }
}

// ============================ launch ============================
extern "C" void kernel_launch(void* const* d_in, const int* in_sizes, int n_in,
                              void* d_out, int out_size)
{
    (void)in_sizes; (void)n_in; (void)out_size;
    const float* hs    = (const float*)d_in[0];
    const float* pos   = (const float*)d_in[1];
    const float* seg   = (const float*)d_in[2];
    const float* mask  = (const float*)d_in[3];
    const float* wq    = (const float*)d_in[4];
    const float* wk    = (const float*)d_in[5];
    const float* wv    = (const float*)d_in[6];
    const float* wr    = (const float*)d_in[7];
    const float* wo    = (const float*)d_in[8];
    const float* rwb   = (const float*)d_in[9];
    const float* rrb   = (const float*)d_in[10];
    const float* rsb   = (const float*)d_in[11];
    const float* segm  = (const float*)d_in[12];
    const float* gamma = (const float*)d_in[13];
    const float* beta  = (const float*)d_in[14];
    float* out = (float*)d_out;

    float *QKVd, *KRd, *PRd, *EF1d, *BWd, *BRd;
    cudaGetSymbolAddress((void**)&QKVd, g_QKV);
    cudaGetSymbolAddress((void**)&KRd, g_KR);
    cudaGetSymbolAddress((void**)&PRd, g_PR);
    cudaGetSymbolAddress((void**)&EF1d, g_EF1);
    cudaGetSymbolAddress((void**)&BWd, g_BW);
    cudaGetSymbolAddress((void**)&BRd, g_BR);

    __nv_bfloat16 *HA, *PA, *AOb, *WB, *QKVb, *KRb;
    cudaGetSymbolAddress((void**)&HA, g_HA);
    cudaGetSymbolAddress((void**)&PA, g_PA);
    cudaGetSymbolAddress((void**)&AOb, g_AOb);
    cudaGetSymbolAddress((void**)&WB, g_WB);
    cudaGetSymbolAddress((void**)&QKVb, g_QKVb);
    cudaGetSymbolAddress((void**)&KRb, g_KRb);

    cudaFuncSetAttribute(gemm_mma, cudaFuncAttributeMaxDynamicSharedMemorySize, GEMM_SMEM);
    cudaFuncSetAttribute(attn_kernel, cudaFuncAttributeMaxDynamicSharedMemorySize, ATTN_SMEM);

    const size_t WSZ = (size_t)HID * HID;

    // Converts (inputs + weights)
    cvt_kernel<<<(IB*HID/4 + 255)/256, 256>>>(hs,  HA, IB*HID/4);
    cvt_kernel<<<(JBR*HID/4 + 255)/256, 256>>>(pos, PA, JBR*HID/4);
    dim3 gt(32, 32), bt(32, 8);
    tcvt_kernel<<<gt, bt>>>(wq, WB + 0*WSZ);
    tcvt_kernel<<<gt, bt>>>(wk, WB + 1*WSZ);
    tcvt_kernel<<<gt, bt>>>(wv, WB + 2*WSZ);
    tcvt_kernel<<<gt, bt>>>(wr, WB + 3*WSZ);
    cvt_kernel<<<(HID*HID/4 + 255)/256, 256>>>(wo, WB + 4*WSZ, HID*HID/4);

    // Fused QKV projection (N = 3072) + KR projection
    dim3 gqkv(QKVW / 128, IB / 128);   // (24, 32)
    gemm_mma<<<gqkv, 256, GEMM_SMEM>>>(HA, WB, QKVd, IB, QKVW, HID);
    dim3 gr(8, 64);
    gemm_mma<<<gr, 256, GEMM_SMEM>>>(PA, WB + 3*WSZ, KRd, JBR, HID, HID);

    // Pre-convert activations for attention
    cvt_kernel<<<(IB*QKVW/4 + 255)/256, 256>>>(QKVd, QKVb, IB*QKVW/4);
    cvt_kernel<<<(JBR*HID/4 + 255)/256, 256>>>(KRd, KRb, JBR*HID/4);

    // Bias precomputes
    ef1_kernel    <<<IB * NH / 4, 128>>>(QKVd, rsb, segm, EF1d);
    rowbias_kernel<<<QL * BSZ * NH / 4, 128>>>(QKVd, QKVW, 1024, rwb, BWd, QL);
    rowbias_kernel<<<PL * BSZ * NH / 4, 128>>>(KRd,  HID,  0,    rrb, BRd, PL);

    // Fused flash attention
    dim3 ga(QL / 64, BNH);             // (8, 128)
    attn_kernel<<<ga, 256, ATTN_SMEM>>>(QKVd, QKVb, KRb, EF1d, BWd, BRd, seg, mask, AOb);

    // Output projection + LN
    dim3 go(8, 32);
    gemm_mma<<<go, 256, GEMM_SMEM>>>(AOb, WB + 4*WSZ, PRd, IB, HID, HID);
    ln_kernel<<<IB, 256>>>(PRd, hs, gamma, beta, out);
}